// round 6
// baseline (speedup 1.0000x reference)
#include <cuda_runtime.h>
#include <cuda_bf16.h>
#include <math.h>

// out[d,l]: l==0 -> h0[d]; l>=1 -> sum_k Re(R[k,d]*p[k,d]^(l-1))
// a_t = c1*a_{t-1} - r^2*a_{t-2}; c1 = 2 r cos(theta).
// Single fused kernel: per (l-chunk, d-tile) block, each warp takes half the
// poles; seeds a(t0), a(t0+1) computed in-register via p^32 binary powering
// (bx uniform per block), then packed f32x2 recurrence (software-pipelined).

#define CHUNK 32

typedef unsigned long long u64p;

__device__ __forceinline__ u64p pk2(float lo, float hi) {
    u64p r; asm("mov.b64 %0, {%1, %2};" : "=l"(r) : "f"(lo), "f"(hi)); return r;
}
__device__ __forceinline__ void upk2(u64p v, float& lo, float& hi) {
    asm("mov.b64 {%0, %1}, %2;" : "=f"(lo), "=f"(hi) : "l"(v));
}
__device__ __forceinline__ u64p mul2(u64p a, u64p b) {
    u64p r; asm("mul.rn.f32x2 %0, %1, %2;" : "=l"(r) : "l"(a), "l"(b)); return r;
}
__device__ __forceinline__ u64p add2(u64p a, u64p b) {
    u64p r; asm("add.rn.f32x2 %0, %1, %2;" : "=l"(r) : "l"(a), "l"(b)); return r;
}
__device__ __forceinline__ u64p fma2(u64p a, u64p b, u64p c) {
    u64p r; asm("fma.rn.f32x2 %0, %1, %2, %3;" : "=l"(r) : "l"(a), "l"(b), "l"(c)); return r;
}

__global__ __launch_bounds__(64, 8) void lh_fused_kernel(
    const float* __restrict__ rr, const float* __restrict__ th,
    const float* __restrict__ Rre, const float* __restrict__ Rim,
    const float* __restrict__ h0, float* __restrict__ out,
    int D, int L, int K)
{
    const int bx   = blockIdx.x;          // l-chunk; exponent 32*bx uniform
    const int l0   = bx * CHUNK;
    const int d0   = blockIdx.y * 32;
    const int lane = threadIdx.x & 31;
    const int wid  = threadIdx.x >> 5;
    const int d    = d0 + lane;

    __shared__ float tile[2][32][CHUNK + 1];

    u64p acc[CHUNK];
    const u64p z = pk2(0.0f, 0.0f);
#pragma unroll
    for (int i = 0; i < CHUNK; ++i) acc[i] = z;

    const int kbeg = wid * (K >> 1);
    const int kend = kbeg + (K >> 1);

    // prefetch first group's inputs
    float rv[4], tv[4], Av[4], Bv[4];
#pragma unroll
    for (int u = 0; u < 4; ++u) {
        const int idx = (kbeg + u) * D + d;
        rv[u] = rr[idx];  tv[u] = th[idx];
        Av[u] = Rre[idx]; Bv[u] = Rim[idx];
    }

    for (int kg = kbeg; kg < kend; kg += 4) {
        float cr_[4], ct_[4], cA[4], cB[4];
#pragma unroll
        for (int u = 0; u < 4; ++u) { cr_[u]=rv[u]; ct_[u]=tv[u]; cA[u]=Av[u]; cB[u]=Bv[u]; }

        // prefetch next group (wrap on last: harmless dummy)
        const int kn = (kg + 4 < kend) ? kg + 4 : kbeg;
#pragma unroll
        for (int u = 0; u < 4; ++u) {
            const int idx = (kn + u) * D + d;
            rv[u] = rr[idx];  tv[u] = th[idx];
            Av[u] = Rre[idx]; Bv[u] = Rim[idx];
        }

        // ---- in-register seeding for 4 poles (independent -> ILP=4) ----
        float sa0[4], sa1[4], sc1[4], sn2[4];
#pragma unroll
        for (int u = 0; u < 4; ++u) {
            const float r  = cr_[u];
            const float Ar = cA[u];
            const float Ai = cB[u];
            float st, ct;
            sincosf(ct_[u], &st, &ct);
            const float pre = r * ct;          // Re(p)
            const float pim = r * st;          // Im(p)
            sc1[u] = 2.0f * pre;
            sn2[u] = -(r * r);

            // q = p^32 (5 complex squarings)
            float qr = pre, qi = pim;
#pragma unroll
            for (int s = 0; s < 5; ++s) {
                float t1 = qi * qi;
                float nr = fmaf(qr, qr, -t1);
                float t2 = qr * qi;
                qi = t2 + t2;
                qr = nr;
            }
            // w = q^bx (binary powering; bx < 64, uniform per block)
            float wr = 1.0f, wi = 0.0f;
            float br = qr, bi = qi;
            int e = bx;
#pragma unroll
            for (int b = 0; b < 6; ++b) {
                if (e & 1) {
                    float nr = fmaf(wr, br, -wi * bi);
                    float ni = fmaf(wr, bi,  wi * br);
                    wr = nr; wi = ni;
                }
                e >>= 1;
                float t1 = bi * bi;
                float nr = fmaf(br, br, -t1);
                float t2 = br * bi;
                bi = t2 + t2;
                br = nr;
            }
            // a1 = Re(R w) = a(32*bx); a0 = Re(R w conj(p))/r^2 = a(32*bx - 1)
            float zr = fmaf(Ar, wr, -Ai * wi);
            float zi = fmaf(Ar, wi,  Ai * wr);
            sa1[u] = zr;
            sa0[u] = __fdividef(fmaf(zr, pre, zi * pim), r * r);
        }

        u64p C1_0 = pk2(sc1[0], sc1[1]);
        u64p C1_1 = pk2(sc1[2], sc1[3]);
        u64p N2_0 = pk2(sn2[0], sn2[1]);
        u64p N2_1 = pk2(sn2[2], sn2[3]);
        u64p A0_0 = pk2(sa0[0], sa0[1]);
        u64p A0_1 = pk2(sa0[2], sa0[3]);
        u64p A1_0 = pk2(sa1[0], sa1[1]);
        u64p A1_1 = pk2(sa1[2], sa1[3]);

        acc[0] = add2(acc[0], add2(A0_0, A0_1));
        acc[1] = add2(acc[1], add2(A1_0, A1_1));

        // software-pipelined accumulate: pair-sum S lands one iter late.
        u64p S = z;
#pragma unroll
        for (int i = 2; i < CHUNK; ++i) {
            u64p m0 = mul2(N2_0, A0_0);
            u64p m1 = mul2(N2_1, A0_1);
            u64p n0 = fma2(C1_0, A1_0, m0);
            u64p n1 = fma2(C1_1, A1_1, m1);
            if (i > 2) acc[i - 1] = add2(acc[i - 1], S);
            S = add2(n0, n1);
            A0_0 = A1_0; A1_0 = n0;
            A0_1 = A1_1; A1_1 = n1;
        }
        acc[CHUNK - 1] = add2(acc[CHUNK - 1], S);
    }

#pragma unroll
    for (int i = 0; i < CHUNK; ++i) {
        float lo, hi;
        upk2(acc[i], lo, hi);
        tile[wid][lane][i] = lo + hi;
    }
    __syncthreads();

    const int total = 32 * CHUNK;
    for (int j = threadIdx.x; j < total; j += 64) {
        int row = j >> 5;            // / CHUNK
        int col = j & (CHUNK - 1);   // % CHUNK
        int l = l0 + col;
        float v = tile[0][row][col] + tile[1][row][col];
        if (l0 == 0 && col == 0) v = h0[d0 + row];
        if (l < L) out[(size_t)(d0 + row) * L + l] = v;
    }
}

extern "C" void kernel_launch(void* const* d_in, const int* in_sizes, int n_in,
                              void* d_out, int out_size)
{
    const float* rr  = (const float*)d_in[0];
    const float* th  = (const float*)d_in[1];
    const float* Rre = (const float*)d_in[2];
    const float* Rim = (const float*)d_in[3];
    const float* h0  = (const float*)d_in[4];
    float* out = (float*)d_out;

    const int D = in_sizes[4];
    const int K = in_sizes[0] / D;
    const int L = out_size / D;
    const int NBX = (L + CHUNK - 1) / CHUNK;

    dim3 grid(NBX, D / 32);
    lh_fused_kernel<<<grid, 64>>>(rr, th, Rre, Rim, h0, out, D, L, K);
}

// round 10
// speedup vs baseline: 1.0978x; 1.0978x over previous
#include <cuda_runtime.h>
#include <cuda_bf16.h>
#include <math.h>

// out[d,l]: l==0 -> h0[d]; l>=1 -> sum_k Re(R[k,d]*p[k,d]^(l-1))
// a_t = c1*a_{t-1} - r^2*a_{t-2}; c1 = 2 r cos(theta).
// Fused kernel, SPAN=64 l per block: seed once per pole (p^64 powering, bx
// uniform), then run the packed f32x2 recurrence across two 32-wide register
// sub-chunks, carrying state; flush each sub-chunk through shared to global.

#define SPAN 64
#define SUB  32
#define NG   4          // pole groups of 4 per warp (K/2 = 16 poles/warp)

typedef unsigned long long u64p;

__device__ __forceinline__ u64p pk2(float lo, float hi) {
    u64p r; asm("mov.b64 %0, {%1, %2};" : "=l"(r) : "f"(lo), "f"(hi)); return r;
}
__device__ __forceinline__ void upk2(u64p v, float& lo, float& hi) {
    asm("mov.b64 {%0, %1}, %2;" : "=f"(lo), "=f"(hi) : "l"(v));
}
__device__ __forceinline__ u64p mul2(u64p a, u64p b) {
    u64p r; asm("mul.rn.f32x2 %0, %1, %2;" : "=l"(r) : "l"(a), "l"(b)); return r;
}
__device__ __forceinline__ u64p add2(u64p a, u64p b) {
    u64p r; asm("add.rn.f32x2 %0, %1, %2;" : "=l"(r) : "l"(a), "l"(b)); return r;
}
__device__ __forceinline__ u64p fma2(u64p a, u64p b, u64p c) {
    u64p r; asm("fma.rn.f32x2 %0, %1, %2, %3;" : "=l"(r) : "l"(a), "l"(b), "l"(c)); return r;
}

__global__ __launch_bounds__(64, 6) void lh_fused_kernel(
    const float* __restrict__ rr, const float* __restrict__ th,
    const float* __restrict__ Rre, const float* __restrict__ Rim,
    const float* __restrict__ h0, float* __restrict__ out,
    int D, int L, int K)
{
    const int bx   = blockIdx.x;          // l-span index (uniform exponent)
    const int l0   = bx * SPAN;
    const int d0   = blockIdx.y * 32;
    const int lane = threadIdx.x & 31;
    const int wid  = threadIdx.x >> 5;
    const int d    = d0 + lane;

    __shared__ float tile[2][32][SUB + 1];

    const int kbeg = wid * (K >> 1);

    // ---- persistent per-group packed state ----
    u64p C1[NG][2], N2[NG][2], A0[NG][2], A1[NG][2];

#pragma unroll
    for (int g = 0; g < NG; ++g) {
        float sa0[4], sa1[4], sc1[4], sn2[4];
#pragma unroll
        for (int u = 0; u < 4; ++u) {
            const int idx = (kbeg + 4 * g + u) * D + d;
            const float r  = rr[idx];
            const float t_ = th[idx];
            const float Ar = Rre[idx];
            const float Ai = Rim[idx];

            float st, ct;
            sincosf(t_, &st, &ct);
            const float pre = r * ct;            // Re(p)
            const float pim = r * st;            // Im(p)
            sc1[u] = 2.0f * pre;
            sn2[u] = -(r * r);

            // q = p^SPAN (6 complex squarings for SPAN=64)
            float qr = pre, qi = pim;
#pragma unroll
            for (int s = 0; s < 6; ++s) {
                float t1 = qi * qi;
                float nr = fmaf(qr, qr, -t1);
                float t2 = qr * qi;
                qi = t2 + t2;
                qr = nr;
            }
            // w = q^bx (binary powering, bx < 64, uniform per block)
            float wr = 1.0f, wi = 0.0f;
            float br = qr, bi = qi;
            int e = bx;
#pragma unroll
            for (int b = 0; b < 6; ++b) {
                if (e & 1) {
                    float nr = fmaf(wr, br, -wi * bi);
                    float ni = fmaf(wr, bi,  wi * br);
                    wr = nr; wi = ni;
                }
                e >>= 1;
                float t1 = bi * bi;
                float nr = fmaf(br, br, -t1);
                float t2 = br * bi;
                bi = t2 + t2;
                br = nr;
            }
            // a1 = Re(R w) = a(l0);  a0 = Re(R w conj(p))/r^2 = a(l0 - 1)
            float zr = fmaf(Ar, wr, -Ai * wi);
            float zi = fmaf(Ar, wi,  Ai * wr);
            sa1[u] = zr;
            sa0[u] = __fdividef(fmaf(zr, pre, zi * pim), r * r);
        }
        C1[g][0] = pk2(sc1[0], sc1[1]);  C1[g][1] = pk2(sc1[2], sc1[3]);
        N2[g][0] = pk2(sn2[0], sn2[1]);  N2[g][1] = pk2(sn2[2], sn2[3]);
        A0[g][0] = pk2(sa0[0], sa0[1]);  A0[g][1] = pk2(sa0[2], sa0[3]);
        A1[g][0] = pk2(sa1[0], sa1[1]);  A1[g][1] = pk2(sa1[2], sa1[3]);
    }

    const u64p z = pk2(0.0f, 0.0f);
    u64p acc[SUB];

#pragma unroll
    for (int sub = 0; sub < SPAN / SUB; ++sub) {
#pragma unroll
        for (int i = 0; i < SUB; ++i) acc[i] = z;

#pragma unroll
        for (int g = 0; g < NG; ++g) {
            u64p a00 = A0[g][0], a01 = A0[g][1];
            u64p a10 = A1[g][0], a11 = A1[g][1];
            const u64p c10 = C1[g][0], c11 = C1[g][1];
            const u64p n20 = N2[g][0], n21 = N2[g][1];
            u64p S = z;

            if (sub == 0) {
                // first two outputs come straight from the seeds
                acc[0] = add2(acc[0], add2(a00, a01));
                acc[1] = add2(acc[1], add2(a10, a11));
#pragma unroll
                for (int i = 2; i < SUB; ++i) {
                    u64p m0 = mul2(n20, a00);
                    u64p m1 = mul2(n21, a01);
                    u64p n0 = fma2(c10, a10, m0);
                    u64p n1 = fma2(c11, a11, m1);
                    if (i > 2) acc[i - 1] = add2(acc[i - 1], S);
                    S = add2(n0, n1);
                    a00 = a10; a10 = n0;
                    a01 = a11; a11 = n1;
                }
            } else {
                // continue the chain: 32 fresh recurrence steps
#pragma unroll
                for (int i = 0; i < SUB; ++i) {
                    u64p m0 = mul2(n20, a00);
                    u64p m1 = mul2(n21, a01);
                    u64p n0 = fma2(c10, a10, m0);
                    u64p n1 = fma2(c11, a11, m1);
                    if (i > 0) acc[i - 1] = add2(acc[i - 1], S);
                    S = add2(n0, n1);
                    a00 = a10; a10 = n0;
                    a01 = a11; a11 = n1;
                }
            }
            acc[SUB - 1] = add2(acc[SUB - 1], S);

            A0[g][0] = a00; A0[g][1] = a01;
            A1[g][0] = a10; A1[g][1] = a11;
        }

        // ---- flush this sub-chunk ----
#pragma unroll
        for (int i = 0; i < SUB; ++i) {
            float lo, hi;
            upk2(acc[i], lo, hi);
            tile[wid][lane][i] = lo + hi;
        }
        __syncthreads();

        const int lbase = l0 + sub * SUB;
        const int total = 32 * SUB;
        for (int j = threadIdx.x; j < total; j += 64) {
            int row = j >> 5;           // / SUB
            int col = j & (SUB - 1);    // % SUB
            int l = lbase + col;
            float v = tile[0][row][col] + tile[1][row][col];
            if (l == 0) v = h0[d0 + row];
            if (l < L) out[(size_t)(d0 + row) * L + l] = v;
        }
        __syncthreads();
    }
}

extern "C" void kernel_launch(void* const* d_in, const int* in_sizes, int n_in,
                              void* d_out, int out_size)
{
    const float* rr  = (const float*)d_in[0];
    const float* th  = (const float*)d_in[1];
    const float* Rre = (const float*)d_in[2];
    const float* Rim = (const float*)d_in[3];
    const float* h0  = (const float*)d_in[4];
    float* out = (float*)d_out;

    const int D = in_sizes[4];
    const int K = in_sizes[0] / D;
    const int L = out_size / D;
    const int NBX = (L + SPAN - 1) / SPAN;

    dim3 grid(NBX, D / 32);
    lh_fused_kernel<<<grid, 64>>>(rr, th, Rre, Rim, h0, out, D, L, K);
}